// round 1
// baseline (speedup 1.0000x reference)
#include <cuda_runtime.h>

// Problem constants (fixed by setup_inputs)
#define N_ROWS 500000
#define D 64
#define K 16
#define TEMP 5.0f

// Pass-1 launch geometry: 592 blocks x 128 threads (4 warps) -> 2368 warps,
// each warp handles 32-row chunks with stride. 500000 = 15625 * 32 exactly.
#define P1_BLOCKS 592
#define P1_THREADS 128
#define P1_WARPS_PER_BLOCK (P1_THREADS / 32)
#define WARPS_TOTAL (P1_BLOCKS * P1_WARPS_PER_BLOCK)
#define CHUNKS (N_ROWS / 32)

// Shared layout per warp (floats):
//   d_s: column-major raw data tile, D rows x 32 lanes padded to 33 -> conflict-free
//   r_s: 32 rows x 16 k, row stride 20 (16B-aligned vector loads, 4-way store conflicts)
#define DS_FLOATS (D * 33)      // 2112
#define RS_FLOATS (32 * 20)     // 640
#define WARP_SMEM (DS_FLOATS + RS_FLOATS)  // 2752 floats = 11008 B

// Device-global scratch (no allocations allowed)
__device__ float g_mu0[K * D];
__device__ float g_cmean[K * D];
__device__ float g_cr[K];

// ---------------------------------------------------------------------------
// Kernel 0: normalize mu_init rows into g_mu0, zero accumulators.
// ---------------------------------------------------------------------------
__global__ void prep_kernel(const float* __restrict__ mu_init) {
    int tid = threadIdx.x;
    int lane = tid & 31;
    int w = tid >> 5;  // 8 warps (256 threads)
    for (int r = w; r < K; r += 8) {
        float v0 = mu_init[r * D + lane];
        float v1 = mu_init[r * D + 32 + lane];
        float ss = v0 * v0 + v1 * v1;
        #pragma unroll
        for (int off = 16; off; off >>= 1)
            ss += __shfl_xor_sync(0xffffffffu, ss, off);
        float inv = rsqrtf(ss);
        g_mu0[r * D + lane] = v0 * inv;
        g_mu0[r * D + 32 + lane] = v1 * inv;
    }
    for (int i = tid; i < K * D; i += blockDim.x) g_cmean[i] = 0.0f;
    if (tid < K) g_cr[tid] = 0.0f;
}

// ---------------------------------------------------------------------------
// Kernel 1 (pass 1): per 32-row chunk per warp:
//   phase A: each lane owns a row; load, sumsq, dist vs mu0 (shared bcast),
//            softmax -> r; stage raw data (col-major) + r*inv in shared.
//   phase B: warp computes rank-32 update of C[16][64] = r^T * d_norm in
//            registers (lane = (kr,jc) owns 4k x 8j sub-tile).
// Register accumulators persist across chunks; one atomicAdd pass at the end.
// ---------------------------------------------------------------------------
__global__ void __launch_bounds__(P1_THREADS, 4)
pass1_kernel(const float* __restrict__ data) {
    __shared__ __align__(16) float mu_s[K * D];
    __shared__ __align__(16) float sw[P1_WARPS_PER_BLOCK * WARP_SMEM];

    int tid = threadIdx.x;
    int lane = tid & 31;
    int wid = tid >> 5;

    for (int i = tid; i < K * D; i += P1_THREADS) mu_s[i] = g_mu0[i];
    __syncthreads();

    float* ds_ = sw + wid * WARP_SMEM;
    float* rs_ = ds_ + DS_FLOATS;
    const float4* mu4 = (const float4*)mu_s;

    const int kr = lane >> 3;   // 0..3 -> k range kr*4 .. kr*4+3
    const int jc = lane & 7;    // 0..7 -> j range jc*8 .. jc*8+7

    float acc[4][8];
    #pragma unroll
    for (int a = 0; a < 4; a++)
        #pragma unroll
        for (int b = 0; b < 8; b++) acc[a][b] = 0.0f;
    float crs[K];
    #pragma unroll
    for (int k = 0; k < K; k++) crs[k] = 0.0f;

    int gw = blockIdx.x * P1_WARPS_PER_BLOCK + wid;

    for (int chunk = gw; chunk < CHUNKS; chunk += WARPS_TOTAL) {
        int row = chunk * 32 + lane;
        const float4* dp = (const float4*)(data + (size_t)row * D);

        // ---- phase A ----
        float dist[K];
        #pragma unroll
        for (int k = 0; k < K; k++) dist[k] = 0.0f;
        float sumsq = 0.0f;

        #pragma unroll 4
        for (int j4 = 0; j4 < 16; j4++) {
            float4 v = dp[j4];
            sumsq += v.x * v.x + v.y * v.y + v.z * v.z + v.w * v.w;
            int c0 = 4 * j4;
            ds_[(c0 + 0) * 33 + lane] = v.x;
            ds_[(c0 + 1) * 33 + lane] = v.y;
            ds_[(c0 + 2) * 33 + lane] = v.z;
            ds_[(c0 + 3) * 33 + lane] = v.w;
            #pragma unroll
            for (int k = 0; k < K; k++) {
                float4 m = mu4[k * 16 + j4];  // broadcast across warp
                dist[k] += v.x * m.x + v.y * m.y + v.z * m.z + v.w * m.w;
            }
        }

        float inv = rsqrtf(sumsq);
        float mx = -1e30f;
        #pragma unroll
        for (int k = 0; k < K; k++) {
            dist[k] *= inv;
            mx = fmaxf(mx, dist[k]);
        }
        float s = 0.0f;
        #pragma unroll
        for (int k = 0; k < K; k++) {
            dist[k] = __expf(TEMP * (dist[k] - mx));
            s += dist[k];
        }
        float is = 1.0f / s;
        #pragma unroll
        for (int k = 0; k < K; k++) {
            float r = dist[k] * is;
            crs[k] += r;
            rs_[lane * 20 + k] = r * inv;  // fold row-norm into r
        }

        __syncwarp();

        // ---- phase B: rank-32 outer-product update ----
        #pragma unroll 4
        for (int rr = 0; rr < 32; rr++) {
            float4 rv = *(const float4*)(rs_ + rr * 20 + kr * 4);
            float dq[8];
            #pragma unroll
            for (int q = 0; q < 8; q++) dq[q] = ds_[(jc * 8 + q) * 33 + rr];
            #pragma unroll
            for (int q = 0; q < 8; q++) {
                acc[0][q] += rv.x * dq[q];
                acc[1][q] += rv.y * dq[q];
                acc[2][q] += rv.z * dq[q];
                acc[3][q] += rv.w * dq[q];
            }
        }
        __syncwarp();
    }

    // warp-reduce cluster_r, one lane commits
    #pragma unroll
    for (int k = 0; k < K; k++) {
        #pragma unroll
        for (int off = 16; off; off >>= 1)
            crs[k] += __shfl_xor_sync(0xffffffffu, crs[k], off);
    }
    if (lane == 0) {
        #pragma unroll
        for (int k = 0; k < K; k++) atomicAdd(&g_cr[k], crs[k]);
    }
    // commit cluster_mean tile
    #pragma unroll
    for (int k4 = 0; k4 < 4; k4++)
        #pragma unroll
        for (int q = 0; q < 8; q++)
            atomicAdd(&g_cmean[(kr * 4 + k4) * D + jc * 8 + q], acc[k4][q]);
}

// ---------------------------------------------------------------------------
// Kernel 2: mu1 = cluster_mean / cluster_r -> written straight into d_out.
// ---------------------------------------------------------------------------
__global__ void finalize_mu_kernel(float* __restrict__ out_mu) {
    for (int i = threadIdx.x; i < K * D; i += blockDim.x)
        out_mu[i] = g_cmean[i] / g_cr[i >> 6];
}

// ---------------------------------------------------------------------------
// Kernel 3 (pass 2): recompute row norm, dist vs mu1, softmax; write r & dist.
// ---------------------------------------------------------------------------
__global__ void pass2_kernel(const float* __restrict__ data,
                             const float* __restrict__ mu,
                             float* __restrict__ r_out,
                             float* __restrict__ dist_out) {
    __shared__ __align__(16) float mu_s[K * D];
    int tid = threadIdx.x;
    for (int i = tid; i < K * D; i += blockDim.x) mu_s[i] = mu[i];
    __syncthreads();

    int row = blockIdx.x * blockDim.x + tid;
    if (row >= N_ROWS) return;

    const float4* dp = (const float4*)(data + (size_t)row * D);
    const float4* mu4 = (const float4*)mu_s;

    float dist[K];
    #pragma unroll
    for (int k = 0; k < K; k++) dist[k] = 0.0f;
    float sumsq = 0.0f;

    #pragma unroll 4
    for (int j4 = 0; j4 < 16; j4++) {
        float4 v = dp[j4];
        sumsq += v.x * v.x + v.y * v.y + v.z * v.z + v.w * v.w;
        #pragma unroll
        for (int k = 0; k < K; k++) {
            float4 m = mu4[k * 16 + j4];
            dist[k] += v.x * m.x + v.y * m.y + v.z * m.z + v.w * m.w;
        }
    }

    float inv = rsqrtf(sumsq);
    float mx = -1e30f;
    #pragma unroll
    for (int k = 0; k < K; k++) {
        dist[k] *= inv;
        mx = fmaxf(mx, dist[k]);
    }
    float r[K];
    float s = 0.0f;
    #pragma unroll
    for (int k = 0; k < K; k++) {
        r[k] = __expf(TEMP * (dist[k] - mx));
        s += r[k];
    }
    float is = 1.0f / s;
    #pragma unroll
    for (int k = 0; k < K; k++) r[k] *= is;

    float4* r4 = (float4*)(r_out + (size_t)row * K);
    float4* d4 = (float4*)(dist_out + (size_t)row * K);
    #pragma unroll
    for (int i = 0; i < 4; i++) {
        r4[i] = make_float4(r[4 * i], r[4 * i + 1], r[4 * i + 2], r[4 * i + 3]);
        d4[i] = make_float4(dist[4 * i], dist[4 * i + 1], dist[4 * i + 2], dist[4 * i + 3]);
    }
}

// ---------------------------------------------------------------------------
// Launch: prep -> pass1 -> finalize_mu -> pass2 (all default stream,
// graph-capturable, no allocations, no syncs).
// Output layout (reference return order): [mu 16*64 | r 500000*16 | dist 500000*16]
// ---------------------------------------------------------------------------
extern "C" void kernel_launch(void* const* d_in, const int* in_sizes, int n_in,
                              void* d_out, int out_size) {
    const float* data = (const float*)d_in[0];
    const float* mu_init = (const float*)d_in[1];
    (void)in_sizes; (void)n_in; (void)out_size;  // shapes fixed; num_iter == 1

    float* out = (float*)d_out;
    float* out_mu = out;
    float* out_r = out + K * D;
    float* out_dist = out + K * D + (size_t)N_ROWS * K;

    prep_kernel<<<1, 256>>>(mu_init);
    pass1_kernel<<<P1_BLOCKS, P1_THREADS>>>(data);
    finalize_mu_kernel<<<1, 256>>>(out_mu);
    pass2_kernel<<<(N_ROWS + 255) / 256, 256>>>(data, out_mu, out_r, out_dist);
}

// round 4
// speedup vs baseline: 1.0958x; 1.0958x over previous
#include <cuda_runtime.h>

// Problem constants (fixed by setup_inputs)
#define N_ROWS 500000
#define D 64
#define K 16
#define TEMP 5.0f

#define TILE_ROWS 128
#define THREADS 128
#define NUM_TILES 3907          // 3906 full tiles + one 32-row tail
#define P1_GRID 592             // 4 blocks/SM * 148 SMs

// Shared staging: row stride 68 floats (17 16B units) -> conflict-free .128 reads
#define DS_STRIDE 68
// mu transposed [c][k], row stride 20 floats (5 units) -> conflict-free
#define MUT_STRIDE 20

// Device-global scratch (no allocations allowed)
__device__ float g_mu0[K * D];
__device__ float g_cmean[K * D];
__device__ float g_cr[K];

__device__ __forceinline__ void cp_async16(float* smem_dst, const float* gsrc) {
    unsigned sa = (unsigned)__cvta_generic_to_shared(smem_dst);
    asm volatile("cp.async.cg.shared.global [%0], [%1], 16;" :: "r"(sa), "l"(gsrc));
}
__device__ __forceinline__ void cp_async_wait_all() {
    asm volatile("cp.async.commit_group;" ::: "memory");
    asm volatile("cp.async.wait_group 0;" ::: "memory");
}

// ---------------------------------------------------------------------------
// Kernel 0: normalize mu_init rows into g_mu0, zero accumulators.
// ---------------------------------------------------------------------------
__global__ void prep_kernel(const float* __restrict__ mu_init) {
    int tid = threadIdx.x;
    int lane = tid & 31;
    int w = tid >> 5;  // 8 warps
    for (int r = w; r < K; r += 8) {
        float v0 = mu_init[r * D + lane];
        float v1 = mu_init[r * D + 32 + lane];
        float ss = v0 * v0 + v1 * v1;
        #pragma unroll
        for (int off = 16; off; off >>= 1)
            ss += __shfl_xor_sync(0xffffffffu, ss, off);
        float inv = rsqrtf(ss);
        g_mu0[r * D + lane] = v0 * inv;
        g_mu0[r * D + 32 + lane] = v1 * inv;
    }
    for (int i = tid; i < K * D; i += blockDim.x) g_cmean[i] = 0.0f;
    if (tid < K) g_cr[tid] = 0.0f;
}

// ---------------------------------------------------------------------------
// Kernel 1 (pass 1): grid-stride over 128-row tiles.
//  stage: cp.async coalesced into padded shared
//  phase A (per warp, 32 rows): lane (rq,kq) computes dist[4 rows][4 k] via
//          warp-GEMM from shared; softmax via quad shuffles -> r
//  phase B: C[16][64] += r^T d, lane (kq2,jo) owns 4k x 8j, r broadcast via SHFL
//  accumulators persist across tiles; atomics once at the end.
// ---------------------------------------------------------------------------
__global__ void __launch_bounds__(THREADS, 4)
pass1_kernel(const float* __restrict__ data) {
    __shared__ __align__(16) float ds[TILE_ROWS * DS_STRIDE];
    __shared__ __align__(16) float mut[D * MUT_STRIDE];

    int tid = threadIdx.x;
    int lane = tid & 31;
    int wid = tid >> 5;
    int rq = lane >> 2, kq = lane & 3;      // phase A mapping
    int kq2 = lane >> 3, jo = lane & 7;     // phase B mapping

    for (int idx = tid; idx < K * D; idx += THREADS) {
        int k = idx >> 6, c = idx & 63;
        mut[c * MUT_STRIDE + k] = g_mu0[idx];
    }
    // (first stage's __syncthreads orders mut writes before any reads)

    float accB[4][8];
    #pragma unroll
    for (int a = 0; a < 4; a++)
        #pragma unroll
        for (int b = 0; b < 8; b++) accB[a][b] = 0.0f;
    float crs[4] = {0.f, 0.f, 0.f, 0.f};

    const float* dsw = ds + wid * 32 * DS_STRIDE;

    for (int tile = blockIdx.x; tile < NUM_TILES; tile += P1_GRID) {
        int base = tile * TILE_ROWS;
        int rows = N_ROWS - base; if (rows > TILE_ROWS) rows = TILE_ROWS;

        __syncthreads();  // previous tile's readers are done
        int nf4 = rows << 4;
        for (int f = tid; f < nf4; f += THREADS) {
            int row = f >> 4, c4 = f & 15;
            cp_async16(ds + row * DS_STRIDE + c4 * 4,
                       data + (size_t)base * D + (size_t)f * 4);
        }
        cp_async_wait_all();
        __syncthreads();

        if (wid * 32 < rows) {
            // ---- phase A: dist = d @ mu0^T (raw d; normalize after) ----
            float acc[4][4];
            #pragma unroll
            for (int i = 0; i < 4; i++)
                #pragma unroll
                for (int j = 0; j < 4; j++) acc[i][j] = 0.0f;

            #pragma unroll
            for (int c4 = 0; c4 < 16; c4++) {
                float4 mv[4];
                #pragma unroll
                for (int cc = 0; cc < 4; cc++)
                    mv[cc] = *(const float4*)(mut + (c4 * 4 + cc) * MUT_STRIDE + kq * 4);
                #pragma unroll
                for (int i = 0; i < 4; i++) {
                    float4 dv = *(const float4*)(dsw + (rq + 8 * i) * DS_STRIDE + c4 * 4);
                    float dc[4] = {dv.x, dv.y, dv.z, dv.w};
                    #pragma unroll
                    for (int cc = 0; cc < 4; cc++) {
                        acc[i][0] += dc[cc] * mv[cc].x;
                        acc[i][1] += dc[cc] * mv[cc].y;
                        acc[i][2] += dc[cc] * mv[cc].z;
                        acc[i][3] += dc[cc] * mv[cc].w;
                    }
                }
            }

            // sumsq: quad-partitioned (each lane does 1/4 of columns), then reduce
            float sumsq[4] = {0.f, 0.f, 0.f, 0.f};
            #pragma unroll
            for (int t = 0; t < 4; t++) {
                #pragma unroll
                for (int i = 0; i < 4; i++) {
                    float4 q = *(const float4*)(dsw + (rq + 8 * i) * DS_STRIDE + (kq + 4 * t) * 4);
                    sumsq[i] += q.x * q.x + q.y * q.y + q.z * q.z + q.w * q.w;
                }
            }
            #pragma unroll
            for (int i = 0; i < 4; i++) {
                sumsq[i] += __shfl_xor_sync(0xffffffffu, sumsq[i], 1);
                sumsq[i] += __shfl_xor_sync(0xffffffffu, sumsq[i], 2);
            }

            // softmax per row; fold inv into stored r (acc becomes r*inv)
            #pragma unroll
            for (int i = 0; i < 4; i++) {
                float inv = rsqrtf(sumsq[i]);
                float d0 = acc[i][0] * inv, d1 = acc[i][1] * inv;
                float d2 = acc[i][2] * inv, d3 = acc[i][3] * inv;
                float mx = fmaxf(fmaxf(d0, d1), fmaxf(d2, d3));
                mx = fmaxf(mx, __shfl_xor_sync(0xffffffffu, mx, 1));
                mx = fmaxf(mx, __shfl_xor_sync(0xffffffffu, mx, 2));
                float e0 = __expf(TEMP * (d0 - mx)), e1 = __expf(TEMP * (d1 - mx));
                float e2 = __expf(TEMP * (d2 - mx)), e3 = __expf(TEMP * (d3 - mx));
                float s = e0 + e1 + e2 + e3;
                s += __shfl_xor_sync(0xffffffffu, s, 1);
                s += __shfl_xor_sync(0xffffffffu, s, 2);
                float is = 1.0f / s;
                float r0 = e0 * is, r1 = e1 * is, r2 = e2 * is, r3 = e3 * is;
                crs[0] += r0; crs[1] += r1; crs[2] += r2; crs[3] += r3;
                acc[i][0] = r0 * inv; acc[i][1] = r1 * inv;
                acc[i][2] = r2 * inv; acc[i][3] = r3 * inv;
            }

            // ---- phase B: accB[k'][j'] += r[rr][k'] * d[rr][j'] ----
            #pragma unroll
            for (int i = 0; i < 4; i++) {
                #pragma unroll
                for (int r8 = 0; r8 < 8; r8++) {
                    int rr = i * 8 + r8;
                    int srcl = (r8 << 2) + kq2;  // phase-A lane holding r[rr][4*kq2+..]
                    float rv0 = __shfl_sync(0xffffffffu, acc[i][0], srcl);
                    float rv1 = __shfl_sync(0xffffffffu, acc[i][1], srcl);
                    float rv2 = __shfl_sync(0xffffffffu, acc[i][2], srcl);
                    float rv3 = __shfl_sync(0xffffffffu, acc[i][3], srcl);
                    const float* dr = dsw + rr * DS_STRIDE + jo * 8;
                    float4 a = *(const float4*)dr;
                    float4 b = *(const float4*)(dr + 4);
                    float av[8] = {a.x, a.y, a.z, a.w, b.x, b.y, b.z, b.w};
                    #pragma unroll
                    for (int q = 0; q < 8; q++) {
                        accB[0][q] += rv0 * av[q];
                        accB[1][q] += rv1 * av[q];
                        accB[2][q] += rv2 * av[q];
                        accB[3][q] += rv3 * av[q];
                    }
                }
            }
        }
    }

    // cluster_r: reduce across rq (lanes sharing kq), lanes 0..3 commit
    #pragma unroll
    for (int j = 0; j < 4; j++) {
        crs[j] += __shfl_xor_sync(0xffffffffu, crs[j], 4);
        crs[j] += __shfl_xor_sync(0xffffffffu, crs[j], 8);
        crs[j] += __shfl_xor_sync(0xffffffffu, crs[j], 16);
    }
    if (lane < 4) {
        #pragma unroll
        for (int j = 0; j < 4; j++) atomicAdd(&g_cr[lane * 4 + j], crs[j]);
    }
    // cluster_mean tile commit (addresses distinct across lanes -> spread)
    #pragma unroll
    for (int j = 0; j < 4; j++)
        #pragma unroll
        for (int q = 0; q < 8; q++)
            atomicAdd(&g_cmean[(4 * kq2 + j) * D + 8 * jo + q], accB[j][q]);
}

// ---------------------------------------------------------------------------
// Kernel 2: mu1 = cluster_mean / cluster_r -> d_out (mu section).
// ---------------------------------------------------------------------------
__global__ void finalize_mu_kernel(float* __restrict__ out_mu) {
    for (int i = threadIdx.x; i < K * D; i += blockDim.x)
        out_mu[i] = g_cmean[i] / g_cr[i >> 6];
}

// ---------------------------------------------------------------------------
// Kernel 3 (pass 2): one tile per block; same warp-GEMM phase A vs mu1,
// softmax; coalesced float4 writes of r and dist.
// ---------------------------------------------------------------------------
__global__ void __launch_bounds__(THREADS, 5)
pass2_kernel(const float* __restrict__ data, const float* __restrict__ mu,
             float* __restrict__ r_out, float* __restrict__ dist_out) {
    __shared__ __align__(16) float ds[TILE_ROWS * DS_STRIDE];
    __shared__ __align__(16) float mut[D * MUT_STRIDE];

    int tid = threadIdx.x;
    int lane = tid & 31;
    int wid = tid >> 5;
    int rq = lane >> 2, kq = lane & 3;

    int tile = blockIdx.x;
    int base = tile * TILE_ROWS;
    int rows = N_ROWS - base; if (rows > TILE_ROWS) rows = TILE_ROWS;

    for (int idx = tid; idx < K * D; idx += THREADS) {
        int k = idx >> 6, c = idx & 63;
        mut[c * MUT_STRIDE + k] = mu[idx];
    }
    int nf4 = rows << 4;
    for (int f = tid; f < nf4; f += THREADS) {
        int row = f >> 4, c4 = f & 15;
        cp_async16(ds + row * DS_STRIDE + c4 * 4,
                   data + (size_t)base * D + (size_t)f * 4);
    }
    cp_async_wait_all();
    __syncthreads();

    if (wid * 32 >= rows) return;
    const float* dsw = ds + wid * 32 * DS_STRIDE;

    float acc[4][4];
    #pragma unroll
    for (int i = 0; i < 4; i++)
        #pragma unroll
        for (int j = 0; j < 4; j++) acc[i][j] = 0.0f;

    #pragma unroll
    for (int c4 = 0; c4 < 16; c4++) {
        float4 mv[4];
        #pragma unroll
        for (int cc = 0; cc < 4; cc++)
            mv[cc] = *(const float4*)(mut + (c4 * 4 + cc) * MUT_STRIDE + kq * 4);
        #pragma unroll
        for (int i = 0; i < 4; i++) {
            float4 dv = *(const float4*)(dsw + (rq + 8 * i) * DS_STRIDE + c4 * 4);
            float dc[4] = {dv.x, dv.y, dv.z, dv.w};
            #pragma unroll
            for (int cc = 0; cc < 4; cc++) {
                acc[i][0] += dc[cc] * mv[cc].x;
                acc[i][1] += dc[cc] * mv[cc].y;
                acc[i][2] += dc[cc] * mv[cc].z;
                acc[i][3] += dc[cc] * mv[cc].w;
            }
        }
    }

    float sumsq[4] = {0.f, 0.f, 0.f, 0.f};
    #pragma unroll
    for (int t = 0; t < 4; t++) {
        #pragma unroll
        for (int i = 0; i < 4; i++) {
            float4 q = *(const float4*)(dsw + (rq + 8 * i) * DS_STRIDE + (kq + 4 * t) * 4);
            sumsq[i] += q.x * q.x + q.y * q.y + q.z * q.z + q.w * q.w;
        }
    }
    #pragma unroll
    for (int i = 0; i < 4; i++) {
        sumsq[i] += __shfl_xor_sync(0xffffffffu, sumsq[i], 1);
        sumsq[i] += __shfl_xor_sync(0xffffffffu, sumsq[i], 2);
    }

    #pragma unroll
    for (int i = 0; i < 4; i++) {
        float inv = rsqrtf(sumsq[i]);
        float d0 = acc[i][0] * inv, d1 = acc[i][1] * inv;
        float d2 = acc[i][2] * inv, d3 = acc[i][3] * inv;
        float mx = fmaxf(fmaxf(d0, d1), fmaxf(d2, d3));
        mx = fmaxf(mx, __shfl_xor_sync(0xffffffffu, mx, 1));
        mx = fmaxf(mx, __shfl_xor_sync(0xffffffffu, mx, 2));
        float e0 = __expf(TEMP * (d0 - mx)), e1 = __expf(TEMP * (d1 - mx));
        float e2 = __expf(TEMP * (d2 - mx)), e3 = __expf(TEMP * (d3 - mx));
        float s = e0 + e1 + e2 + e3;
        s += __shfl_xor_sync(0xffffffffu, s, 1);
        s += __shfl_xor_sync(0xffffffffu, s, 2);
        float is = 1.0f / s;

        size_t off = (size_t)(base + wid * 32 + rq + 8 * i) * K + kq * 4;
        *(float4*)(r_out + off) = make_float4(e0 * is, e1 * is, e2 * is, e3 * is);
        *(float4*)(dist_out + off) = make_float4(d0, d1, d2, d3);
    }
}

// ---------------------------------------------------------------------------
// Launch: prep -> pass1 -> finalize_mu -> pass2.
// Output layout (reference return order): [mu 16*64 | r 500000*16 | dist 500000*16]
// ---------------------------------------------------------------------------
extern "C" void kernel_launch(void* const* d_in, const int* in_sizes, int n_in,
                              void* d_out, int out_size) {
    const float* data = (const float*)d_in[0];
    const float* mu_init = (const float*)d_in[1];
    (void)in_sizes; (void)n_in; (void)out_size;  // shapes fixed; num_iter == 1

    float* out = (float*)d_out;
    float* out_mu = out;
    float* out_r = out + K * D;
    float* out_dist = out + K * D + (size_t)N_ROWS * K;

    prep_kernel<<<1, 256>>>(mu_init);
    pass1_kernel<<<P1_GRID, THREADS>>>(data);
    finalize_mu_kernel<<<1, 256>>>(out_mu);
    pass2_kernel<<<NUM_TILES, THREADS>>>(data, out_mu, out_r, out_dist);
}

// round 5
// speedup vs baseline: 1.2712x; 1.1600x over previous
#include <cuda_runtime.h>

// Problem constants (fixed by setup_inputs)
#define N_ROWS 500000
#define D 64
#define K 16
#define TEMP 5.0f

#define TILE_ROWS 128
#define THREADS 128
#define NUM_TILES 3907          // 3906 full tiles + one 32-row tail
#define GRID 444                // 3 blocks/SM * 148 SMs (persistent, pipelined)

// Shared staging: row stride 68 floats (17 16B units) -> conflict-free .128 reads
#define DS_STRIDE 68
// mu transposed [c][k], row stride 20 floats (5 units) -> conflict-free
#define MUT_STRIDE 20

#define BUF_FLOATS (TILE_ROWS * DS_STRIDE)                    // 8704
#define SMEM_BYTES ((2 * BUF_FLOATS + D * MUT_STRIDE) * 4)    // 74752 B

// Device-global scratch (no allocations allowed)
__device__ float g_mu0[K * D];
__device__ float g_cmean[K * D];
__device__ float g_cr[K];

__device__ __forceinline__ void cp_async16(float* smem_dst, const float* gsrc) {
    unsigned sa = (unsigned)__cvta_generic_to_shared(smem_dst);
    asm volatile("cp.async.cg.shared.global [%0], [%1], 16;" :: "r"(sa), "l"(gsrc));
}
__device__ __forceinline__ void cp_commit() {
    asm volatile("cp.async.commit_group;" ::: "memory");
}
template <int N>
__device__ __forceinline__ void cp_wait() {
    asm volatile("cp.async.wait_group %0;" :: "n"(N) : "memory");
}

__device__ __forceinline__ void load_tile(float* buf, const float* __restrict__ data,
                                          int base, int rows, int tid) {
    int nf4 = rows << 4;
    for (int f = tid; f < nf4; f += THREADS) {
        int row = f >> 4, c4 = f & 15;
        cp_async16(buf + row * DS_STRIDE + c4 * 4,
                   data + (size_t)base * D + (size_t)f * 4);
    }
}

// ---------------------------------------------------------------------------
// Kernel 0: normalize mu_init rows into g_mu0, zero accumulators.
// ---------------------------------------------------------------------------
__global__ void prep_kernel(const float* __restrict__ mu_init) {
    int tid = threadIdx.x;
    int lane = tid & 31;
    int w = tid >> 5;  // 8 warps
    for (int r = w; r < K; r += 8) {
        float v0 = mu_init[r * D + lane];
        float v1 = mu_init[r * D + 32 + lane];
        float ss = v0 * v0 + v1 * v1;
        #pragma unroll
        for (int off = 16; off; off >>= 1)
            ss += __shfl_xor_sync(0xffffffffu, ss, off);
        float inv = rsqrtf(ss);
        g_mu0[r * D + lane] = v0 * inv;
        g_mu0[r * D + 32 + lane] = v1 * inv;
    }
    for (int i = tid; i < K * D; i += blockDim.x) g_cmean[i] = 0.0f;
    if (tid < K) g_cr[tid] = 0.0f;
}

// ---------------------------------------------------------------------------
// Kernel 1 (pass 1): persistent blocks, double-buffered cp.async pipeline.
//  phase A (per warp, 32 rows): lane (rq,kq) computes dist[4 rows][4 k];
//  softmax via quad shuffles -> r; phase B: C[16][64] += r^T d with r via SHFL.
//  Register accumulators persist; atomics once at the end.
// ---------------------------------------------------------------------------
__global__ void __launch_bounds__(THREADS)
pass1_kernel(const float* __restrict__ data) {
    extern __shared__ __align__(16) float sm[];
    float* buf0 = sm;
    float* buf1 = sm + BUF_FLOATS;
    float* mut  = sm + 2 * BUF_FLOATS;

    int tid = threadIdx.x;
    int lane = tid & 31;
    int wid = tid >> 5;
    int rq = lane >> 2, kq = lane & 3;      // phase A mapping
    int kq2 = lane >> 3, jo = lane & 7;     // phase B mapping

    for (int idx = tid; idx < K * D; idx += THREADS) {
        int k = idx >> 6, c = idx & 63;
        mut[c * MUT_STRIDE + k] = g_mu0[idx];
    }
    // (first pipeline __syncthreads orders mut writes before reads)

    float accB[4][8];
    #pragma unroll
    for (int a = 0; a < 4; a++)
        #pragma unroll
        for (int b = 0; b < 8; b++) accB[a][b] = 0.0f;
    float crs[4] = {0.f, 0.f, 0.f, 0.f};

    // prologue: load first tile into buf0
    {
        int base = blockIdx.x * TILE_ROWS;
        int rows = N_ROWS - base; if (rows > TILE_ROWS) rows = TILE_ROWS;
        load_tile(buf0, data, base, rows, tid);
        cp_commit();
    }

    int ib = 0;
    for (int t = blockIdx.x; t < NUM_TILES; t += GRID, ib ^= 1) {
        int tn = t + GRID;
        if (tn < NUM_TILES) {
            int nbase = tn * TILE_ROWS;
            int nrows = N_ROWS - nbase; if (nrows > TILE_ROWS) nrows = TILE_ROWS;
            load_tile(ib ? buf0 : buf1, data, nbase, nrows, tid);
            cp_commit();
            cp_wait<1>();   // tile t ready (loads retire in order)
        } else {
            cp_wait<0>();
        }
        __syncthreads();

        int base = t * TILE_ROWS;
        int rows = N_ROWS - base; if (rows > TILE_ROWS) rows = TILE_ROWS;
        const float* dsw = (ib ? buf1 : buf0) + wid * 32 * DS_STRIDE;

        if (wid * 32 < rows) {
            // ---- phase A: dist = d @ mu0^T (raw d; normalize after) ----
            float acc[4][4];
            #pragma unroll
            for (int i = 0; i < 4; i++)
                #pragma unroll
                for (int j = 0; j < 4; j++) acc[i][j] = 0.0f;

            #pragma unroll
            for (int c4 = 0; c4 < 16; c4++) {
                float4 mv[4];
                #pragma unroll
                for (int cc = 0; cc < 4; cc++)
                    mv[cc] = *(const float4*)(mut + (c4 * 4 + cc) * MUT_STRIDE + kq * 4);
                #pragma unroll
                for (int i = 0; i < 4; i++) {
                    float4 dv = *(const float4*)(dsw + (rq + 8 * i) * DS_STRIDE + c4 * 4);
                    float dc[4] = {dv.x, dv.y, dv.z, dv.w};
                    #pragma unroll
                    for (int cc = 0; cc < 4; cc++) {
                        acc[i][0] += dc[cc] * mv[cc].x;
                        acc[i][1] += dc[cc] * mv[cc].y;
                        acc[i][2] += dc[cc] * mv[cc].z;
                        acc[i][3] += dc[cc] * mv[cc].w;
                    }
                }
            }

            // sumsq: quad-partitioned, then reduce over kq
            float sumsq[4] = {0.f, 0.f, 0.f, 0.f};
            #pragma unroll
            for (int tq = 0; tq < 4; tq++) {
                #pragma unroll
                for (int i = 0; i < 4; i++) {
                    float4 q = *(const float4*)(dsw + (rq + 8 * i) * DS_STRIDE + (kq + 4 * tq) * 4);
                    sumsq[i] += q.x * q.x + q.y * q.y + q.z * q.z + q.w * q.w;
                }
            }
            #pragma unroll
            for (int i = 0; i < 4; i++) {
                sumsq[i] += __shfl_xor_sync(0xffffffffu, sumsq[i], 1);
                sumsq[i] += __shfl_xor_sync(0xffffffffu, sumsq[i], 2);
            }

            // softmax per row; fold inv into stored r (acc becomes r*inv)
            #pragma unroll
            for (int i = 0; i < 4; i++) {
                float inv = rsqrtf(sumsq[i]);
                float d0 = acc[i][0] * inv, d1 = acc[i][1] * inv;
                float d2 = acc[i][2] * inv, d3 = acc[i][3] * inv;
                float mx = fmaxf(fmaxf(d0, d1), fmaxf(d2, d3));
                mx = fmaxf(mx, __shfl_xor_sync(0xffffffffu, mx, 1));
                mx = fmaxf(mx, __shfl_xor_sync(0xffffffffu, mx, 2));
                float e0 = __expf(TEMP * (d0 - mx)), e1 = __expf(TEMP * (d1 - mx));
                float e2 = __expf(TEMP * (d2 - mx)), e3 = __expf(TEMP * (d3 - mx));
                float s = e0 + e1 + e2 + e3;
                s += __shfl_xor_sync(0xffffffffu, s, 1);
                s += __shfl_xor_sync(0xffffffffu, s, 2);
                float is = 1.0f / s;
                float r0 = e0 * is, r1 = e1 * is, r2 = e2 * is, r3 = e3 * is;
                crs[0] += r0; crs[1] += r1; crs[2] += r2; crs[3] += r3;
                acc[i][0] = r0 * inv; acc[i][1] = r1 * inv;
                acc[i][2] = r2 * inv; acc[i][3] = r3 * inv;
            }

            // ---- phase B: accB[k'][j'] += r[rr][k'] * d[rr][j'] ----
            #pragma unroll
            for (int i = 0; i < 4; i++) {
                #pragma unroll
                for (int r8 = 0; r8 < 8; r8++) {
                    int rr = i * 8 + r8;
                    int srcl = (r8 << 2) + kq2;  // phase-A lane holding r[rr][4*kq2+..]
                    float rv0 = __shfl_sync(0xffffffffu, acc[i][0], srcl);
                    float rv1 = __shfl_sync(0xffffffffu, acc[i][1], srcl);
                    float rv2 = __shfl_sync(0xffffffffu, acc[i][2], srcl);
                    float rv3 = __shfl_sync(0xffffffffu, acc[i][3], srcl);
                    const float* dr = dsw + rr * DS_STRIDE + jo * 8;
                    float4 a = *(const float4*)dr;
                    float4 b = *(const float4*)(dr + 4);
                    float av[8] = {a.x, a.y, a.z, a.w, b.x, b.y, b.z, b.w};
                    #pragma unroll
                    for (int q = 0; q < 8; q++) {
                        accB[0][q] += rv0 * av[q];
                        accB[1][q] += rv1 * av[q];
                        accB[2][q] += rv2 * av[q];
                        accB[3][q] += rv3 * av[q];
                    }
                }
            }
        }
        __syncthreads();  // all warps done with buf[ib] before it is re-filled
    }

    // cluster_r: reduce across rq (lanes sharing kq), lanes 0..3 commit
    #pragma unroll
    for (int j = 0; j < 4; j++) {
        crs[j] += __shfl_xor_sync(0xffffffffu, crs[j], 4);
        crs[j] += __shfl_xor_sync(0xffffffffu, crs[j], 8);
        crs[j] += __shfl_xor_sync(0xffffffffu, crs[j], 16);
    }
    if (lane < 4) {
        #pragma unroll
        for (int j = 0; j < 4; j++) atomicAdd(&g_cr[lane * 4 + j], crs[j]);
    }
    #pragma unroll
    for (int j = 0; j < 4; j++)
        #pragma unroll
        for (int q = 0; q < 8; q++)
            atomicAdd(&g_cmean[(4 * kq2 + j) * D + 8 * jo + q], accB[j][q]);
}

// ---------------------------------------------------------------------------
// Kernel 2: mu1 = cluster_mean / cluster_r -> d_out (mu section).
// ---------------------------------------------------------------------------
__global__ void finalize_mu_kernel(float* __restrict__ out_mu) {
    for (int i = threadIdx.x; i < K * D; i += blockDim.x)
        out_mu[i] = g_cmean[i] / g_cr[i >> 6];
}

// ---------------------------------------------------------------------------
// Kernel 3 (pass 2): persistent blocks, double-buffered; phase A vs mu1,
// softmax; coalesced float4 writes of r and dist.
// ---------------------------------------------------------------------------
__global__ void __launch_bounds__(THREADS)
pass2_kernel(const float* __restrict__ data, const float* __restrict__ mu,
             float* __restrict__ r_out, float* __restrict__ dist_out) {
    extern __shared__ __align__(16) float sm[];
    float* buf0 = sm;
    float* buf1 = sm + BUF_FLOATS;
    float* mut  = sm + 2 * BUF_FLOATS;

    int tid = threadIdx.x;
    int lane = tid & 31;
    int wid = tid >> 5;
    int rq = lane >> 2, kq = lane & 3;

    for (int idx = tid; idx < K * D; idx += THREADS) {
        int k = idx >> 6, c = idx & 63;
        mut[c * MUT_STRIDE + k] = mu[idx];
    }

    {
        int base = blockIdx.x * TILE_ROWS;
        int rows = N_ROWS - base; if (rows > TILE_ROWS) rows = TILE_ROWS;
        load_tile(buf0, data, base, rows, tid);
        cp_commit();
    }

    int ib = 0;
    for (int t = blockIdx.x; t < NUM_TILES; t += GRID, ib ^= 1) {
        int tn = t + GRID;
        if (tn < NUM_TILES) {
            int nbase = tn * TILE_ROWS;
            int nrows = N_ROWS - nbase; if (nrows > TILE_ROWS) nrows = TILE_ROWS;
            load_tile(ib ? buf0 : buf1, data, nbase, nrows, tid);
            cp_commit();
            cp_wait<1>();
        } else {
            cp_wait<0>();
        }
        __syncthreads();

        int base = t * TILE_ROWS;
        int rows = N_ROWS - base; if (rows > TILE_ROWS) rows = TILE_ROWS;
        const float* dsw = (ib ? buf1 : buf0) + wid * 32 * DS_STRIDE;

        if (wid * 32 < rows) {
            float acc[4][4];
            #pragma unroll
            for (int i = 0; i < 4; i++)
                #pragma unroll
                for (int j = 0; j < 4; j++) acc[i][j] = 0.0f;

            #pragma unroll
            for (int c4 = 0; c4 < 16; c4++) {
                float4 mv[4];
                #pragma unroll
                for (int cc = 0; cc < 4; cc++)
                    mv[cc] = *(const float4*)(mut + (c4 * 4 + cc) * MUT_STRIDE + kq * 4);
                #pragma unroll
                for (int i = 0; i < 4; i++) {
                    float4 dv = *(const float4*)(dsw + (rq + 8 * i) * DS_STRIDE + c4 * 4);
                    float dc[4] = {dv.x, dv.y, dv.z, dv.w};
                    #pragma unroll
                    for (int cc = 0; cc < 4; cc++) {
                        acc[i][0] += dc[cc] * mv[cc].x;
                        acc[i][1] += dc[cc] * mv[cc].y;
                        acc[i][2] += dc[cc] * mv[cc].z;
                        acc[i][3] += dc[cc] * mv[cc].w;
                    }
                }
            }

            float sumsq[4] = {0.f, 0.f, 0.f, 0.f};
            #pragma unroll
            for (int tq = 0; tq < 4; tq++) {
                #pragma unroll
                for (int i = 0; i < 4; i++) {
                    float4 q = *(const float4*)(dsw + (rq + 8 * i) * DS_STRIDE + (kq + 4 * tq) * 4);
                    sumsq[i] += q.x * q.x + q.y * q.y + q.z * q.z + q.w * q.w;
                }
            }
            #pragma unroll
            for (int i = 0; i < 4; i++) {
                sumsq[i] += __shfl_xor_sync(0xffffffffu, sumsq[i], 1);
                sumsq[i] += __shfl_xor_sync(0xffffffffu, sumsq[i], 2);
            }

            #pragma unroll
            for (int i = 0; i < 4; i++) {
                float inv = rsqrtf(sumsq[i]);
                float d0 = acc[i][0] * inv, d1 = acc[i][1] * inv;
                float d2 = acc[i][2] * inv, d3 = acc[i][3] * inv;
                float mx = fmaxf(fmaxf(d0, d1), fmaxf(d2, d3));
                mx = fmaxf(mx, __shfl_xor_sync(0xffffffffu, mx, 1));
                mx = fmaxf(mx, __shfl_xor_sync(0xffffffffu, mx, 2));
                float e0 = __expf(TEMP * (d0 - mx)), e1 = __expf(TEMP * (d1 - mx));
                float e2 = __expf(TEMP * (d2 - mx)), e3 = __expf(TEMP * (d3 - mx));
                float s = e0 + e1 + e2 + e3;
                s += __shfl_xor_sync(0xffffffffu, s, 1);
                s += __shfl_xor_sync(0xffffffffu, s, 2);
                float is = 1.0f / s;

                size_t off = (size_t)(base + wid * 32 + rq + 8 * i) * K + kq * 4;
                *(float4*)(r_out + off) = make_float4(e0 * is, e1 * is, e2 * is, e3 * is);
                *(float4*)(dist_out + off) = make_float4(d0, d1, d2, d3);
            }
        }
        __syncthreads();
    }
}

// ---------------------------------------------------------------------------
// Launch: prep -> pass1 -> finalize_mu -> pass2.
// Output layout (reference return order): [mu 16*64 | r 500000*16 | dist 500000*16]
// ---------------------------------------------------------------------------
extern "C" void kernel_launch(void* const* d_in, const int* in_sizes, int n_in,
                              void* d_out, int out_size) {
    const float* data = (const float*)d_in[0];
    const float* mu_init = (const float*)d_in[1];
    (void)in_sizes; (void)n_in; (void)out_size;  // shapes fixed; num_iter == 1

    float* out = (float*)d_out;
    float* out_mu = out;
    float* out_r = out + K * D;
    float* out_dist = out + K * D + (size_t)N_ROWS * K;

    // >48KB dynamic shared requires opting in (host-side attribute; no alloc).
    cudaFuncSetAttribute(pass1_kernel, cudaFuncAttributeMaxDynamicSharedMemorySize, SMEM_BYTES);
    cudaFuncSetAttribute(pass2_kernel, cudaFuncAttributeMaxDynamicSharedMemorySize, SMEM_BYTES);

    prep_kernel<<<1, 256>>>(mu_init);
    pass1_kernel<<<GRID, THREADS, SMEM_BYTES>>>(data);
    finalize_mu_kernel<<<1, 256>>>(out_mu);
    pass2_kernel<<<GRID, THREADS, SMEM_BYTES>>>(data, out_mu, out_r, out_dist);
}